// round 16
// baseline (speedup 1.0000x reference)
#include <cuda_runtime.h>

// Reference math: dx = 0  =>  s^2 = -dt^2 <= 0 everywhere  =>  spacelike_mask == 0
// => penalty == 0 => total_loss = base_loss + 0.01 * 0 = base_loss (bit-exact in fp32).
// attn_weights (d_in[0], ~302M floats) is dead input; live dependence is 4 bytes.
//
// FINAL (converged; reconfirmed R10-R15): captured graph = one SM-path kernel
// node copying the scalar. Identical-source samples across holds:
//   kernel node (SM): {4.864, 4.608, 4.608, 4.864, 4.864, 4.576, 4.608, 4.576}
//                     mean 4.70 µs, sigma ~0.13, no tail — stationary
//   memcpy node (CE): {4.608, 4.864, 6.912} µs — CE-path tail observed
// ncu: all pipes 0%, HBM 0%, regs=16 (floor); envelope drifts 3.33-3.78 µs
// across holds for identical SASS => residual design deltas unmeasurable.
// Floors: 4-byte live dependence / 1 mandatory node (d_out poisoned
// pre-timing) / tail-free node type. Holding the fixpoint.

__global__ __launch_bounds__(32)
void spacetime_loss_copy(const float* __restrict__ base_loss,
                         float* __restrict__ out) {
    if (threadIdx.x == 0) out[0] = base_loss[0];
}

extern "C" void kernel_launch(void* const* d_in, const int* in_sizes, int n_in,
                              void* d_out, int out_size) {
    // d_in[1] = base_loss scalar f32; d_out[0] = total_loss f32
    spacetime_loss_copy<<<1, 32>>>((const float*)d_in[1], (float*)d_out);
}

// round 17
// speedup vs baseline: 1.0629x; 1.0629x over previous
#include <cuda_runtime.h>

// Reference math: dx = 0  =>  s^2 = -dt^2 <= 0 everywhere  =>  spacelike_mask == 0
// => penalty == 0 => total_loss = base_loss + 0.01 * 0 = base_loss (bit-exact in fp32).
// attn_weights (d_in[0], ~302M floats) is dead input; live dependence is 4 bytes.
//
// FINAL (converged; reconfirmed R10-R16): captured graph = one SM-path kernel
// node copying the scalar. Identical-source samples across holds:
//   kernel node (SM): {4.864, 4.608, 4.608, 4.864, 4.864, 4.576, 4.608,
//                      4.576, 4.864} µs — mean 4.73, sigma ~0.14, no tail
//   memcpy node (CE): {4.608, 4.864, 6.912} µs — CE-path tail observed
// ncu: all pipes 0%, HBM 0%, regs=16 (floor); envelope drifts 3.33-3.94 µs
// across holds for identical SASS (~600 ns environmental wobble) => residual
// design deltas unmeasurable. Floors: 4-byte live dependence / 1 mandatory
// node (d_out poisoned pre-timing) / tail-free node type. Holding fixpoint.

__global__ __launch_bounds__(32)
void spacetime_loss_copy(const float* __restrict__ base_loss,
                         float* __restrict__ out) {
    if (threadIdx.x == 0) out[0] = base_loss[0];
}

extern "C" void kernel_launch(void* const* d_in, const int* in_sizes, int n_in,
                              void* d_out, int out_size) {
    // d_in[1] = base_loss scalar f32; d_out[0] = total_loss f32
    spacetime_loss_copy<<<1, 32>>>((const float*)d_in[1], (float*)d_out);
}